// round 5
// baseline (speedup 1.0000x reference)
#include <cuda_runtime.h>
#include <math.h>

#define BB 32
#define CC 256
#define HWD 96
#define ROW4 (HWD/4)         // 24
#define PLANE (HWD*HWD)      // 9216
#define NPLANES (BB*CC)      // 8192
#define KK 9
#define W2ROWS (CC*KK)       // 2304
#define NB 296               // 2 blocks/SM * 148 SMs — all resident (spin-safety)

// scratch — zero-initialized at module load; counters are monotonic across
// launches (epoch derived from ticket), so no per-launch reset is needed.
__device__ float        g_pooled[NPLANES];
__device__ float        g_wdyn[NPLANES * KK];
__device__ unsigned int g_cnt[BB];    // pool arrivals (monotonic)
__device__ unsigned int g_flag[BB];   // dyn completions (monotonic)

__global__ __launch_bounds__(256, 2) void fused_kernel(
    const float* __restrict__ x,
    const float* __restrict__ w1,
    const float* __restrict__ b1,
    const float* __restrict__ w2,
    const float* __restrict__ b2,
    float* __restrict__ out)
{
    __shared__ float s[PLANE];        // 36864 B: the staged plane
    __shared__ float ps[CC];          // pooled vector (dyn executor)
    __shared__ float hs[CC];          // hidden vector (dyn executor)
    __shared__ float ws[8];
    __shared__ unsigned int s_old;

    const int tid  = threadIdx.x;
    const int lane = tid & 31, wid = tid >> 5;

    for (int task = blockIdx.x; task < NPLANES; task += NB) {
        const int b = task >> 8;      // batch
        // ---------------- phase 1: load plane -> smem, pool in-flight ------
        const float4* __restrict__ xp =
            reinterpret_cast<const float4*>(x + (size_t)task * PLANE);
        float4* sp = reinterpret_cast<float4*>(s);
        float sum = 0.f;
#pragma unroll
        for (int it = 0; it < 9; ++it) {
            float4 v = __ldcs(&xp[tid + it * 256]);
            sp[tid + it * 256] = v;
            sum += (v.x + v.y) + (v.z + v.w);
        }
#pragma unroll
        for (int o = 16; o > 0; o >>= 1)
            sum += __shfl_xor_sync(0xffffffffu, sum, o);
        if (lane == 0) ws[wid] = sum;
        __syncthreads();
        if (tid == 0) {
            float t = 0.f;
#pragma unroll
            for (int i = 0; i < 8; ++i) t += ws[i];
            g_pooled[task] = t * (1.0f / (float)PLANE);
            __threadfence();                       // release pooled value
            s_old = atomicAdd(&g_cnt[b], 1u);      // ticket
        }
        __syncthreads();
        const unsigned int old   = s_old;
        const unsigned int epoch = old >> 8;       // launch index for batch b
        const bool is_last = ((old & 255u) == 255u);

        // ---------------- phase 2: dyn (last arriver) or wait --------------
        if (is_last) {
            __threadfence();                        // acquire all pooled[b]
            ps[tid] = g_pooled[b * CC + tid];
            __syncthreads();
            {
                float acc = b1[tid];
                const float4* __restrict__ wr =
                    reinterpret_cast<const float4*>(w1 + (size_t)tid * CC);
                const float4* __restrict__ pv = reinterpret_cast<const float4*>(ps);
#pragma unroll 8
                for (int k = 0; k < CC / 4; ++k) {
                    float4 a = pv[k]; float4 w = wr[k];
                    acc += a.x * w.x + a.y * w.y + a.z * w.z + a.w * w.w;
                }
                hs[tid] = 0.5f * acc * (1.0f + erff(acc * 0.70710678118654752f));
            }
            __syncthreads();
            const float4* __restrict__ hv = reinterpret_cast<const float4*>(hs);
#pragma unroll
            for (int r0 = 0; r0 < KK; ++r0) {
                const int r = r0 * 256 + tid;
                float acc = b2[r];
                const float4* __restrict__ wr =
                    reinterpret_cast<const float4*>(w2 + (size_t)r * CC);
#pragma unroll 8
                for (int k = 0; k < CC / 4; ++k) {
                    float4 a = hv[k]; float4 w = wr[k];
                    acc += a.x * w.x + a.y * w.y + a.z * w.z + a.w * w.w;
                }
                g_wdyn[(size_t)b * W2ROWS + r] = acc;
            }
            __syncthreads();
            if (tid == 0) {
                __threadfence();                    // release wdyn
                atomicAdd(&g_flag[b], 1u);
            }
        } else {
            if (tid == 0) {
                while (*(volatile unsigned int*)&g_flag[b] <= epoch)
                    __nanosleep(256);
                __threadfence();                    // acquire wdyn
            }
        }
        __syncthreads();

        // ---------------- phase 3: conv from smem, stream out ---------------
        float w[KK];
        const float* __restrict__ wd = g_wdyn + (size_t)task * KK;
#pragma unroll
        for (int i = 0; i < KK; ++i) w[i] = wd[i];

        float4* __restrict__ o4 =
            reinterpret_cast<float4*>(out + (size_t)task * PLANE);
#pragma unroll
        for (int it = 0; it < 9; ++it) {
            const int p4 = tid + it * 256;          // [0, 2304)
            const int y  = p4 / ROW4;
            const int x4 = p4 - y * ROW4;
            const int xb = x4 * 4;

            const int ym = (y == 0) ? 1 : y - 1;            // reflect
            const int yp = (y == HWD - 1) ? HWD - 2 : y + 1;
            const int rows[3] = { ym * HWD, y * HWD, yp * HWD };

            float4 acc = make_float4(0.f, 0.f, 0.f, 0.f);
#pragma unroll
            for (int k = 0; k < 3; ++k) {
                const int rb = rows[k];
                const float wl = w[3 * k + 0];
                const float wc = w[3 * k + 1];
                const float wr = w[3 * k + 2];
                const float4 c = *reinterpret_cast<const float4*>(s + rb + xb);
                const float l = (x4 == 0)        ? c.y : s[rb + xb - 1];
                const float r = (x4 == ROW4 - 1) ? c.z : s[rb + xb + 4];
                acc.x += l   * wl + c.x * wc + c.y * wr;
                acc.y += c.x * wl + c.y * wc + c.z * wr;
                acc.z += c.y * wl + c.z * wc + c.w * wr;
                acc.w += c.z * wl + c.w * wc + r   * wr;
            }
            __stcs(&o4[p4], acc);
        }
        __syncthreads();   // protect s before next round overwrites it
    }
}

// ---------------------------------------------------------------------------
extern "C" void kernel_launch(void* const* d_in, const int* in_sizes, int n_in,
                              void* d_out, int out_size) {
    const float* x  = (const float*)d_in[0];   // (32,256,96,96)
    const float* w1 = (const float*)d_in[1];   // (256,256)
    const float* b1 = (const float*)d_in[2];   // (256,)
    const float* w2 = (const float*)d_in[3];   // (2304,256)
    const float* b2 = (const float*)d_in[4];   // (2304,)
    float* out = (float*)d_out;

    fused_kernel<<<NB, 256>>>(x, w1, b1, w2, b2, out);
}

// round 6
// speedup vs baseline: 16.5952x; 16.5952x over previous
#include <cuda_runtime.h>
#include <math.h>

#define BB 32
#define CC 256
#define HWD 96
#define ROW4 (HWD/4)         // 24 float4 per row
#define PLANE (HWD*HWD)      // 9216
#define NPLANES (BB*CC)      // 8192
#define KK 9
#define W2ROWS (CC*KK)       // 2304

// scratch (no allocations allowed)
__device__ float g_pooled[BB*CC];
__device__ float g_wdyn[BB*CC*KK];

// ---------------------------------------------------------------------------
// Kernel 1: global average pool per (b,c) plane. 1 block = 1 plane.
// Measured at ~84% DRAM roofline.
// ---------------------------------------------------------------------------
__global__ __launch_bounds__(256) void pool_kernel(const float* __restrict__ x) {
    const int plane = blockIdx.x;
    const float4* __restrict__ xp =
        reinterpret_cast<const float4*>(x + (size_t)plane * PLANE);
    float sum = 0.f;
#pragma unroll
    for (int it = 0; it < 9; ++it) {
        float4 v = xp[threadIdx.x + it * 256];
        sum += (v.x + v.y) + (v.z + v.w);
    }
#pragma unroll
    for (int o = 16; o > 0; o >>= 1)
        sum += __shfl_xor_sync(0xffffffffu, sum, o);
    __shared__ float ws[8];
    const int lane = threadIdx.x & 31, wid = threadIdx.x >> 5;
    if (lane == 0) ws[wid] = sum;
    __syncthreads();
    if (threadIdx.x == 0) {
        float t = 0.f;
#pragma unroll
        for (int i = 0; i < 8; ++i) t += ws[i];
        g_pooled[plane] = t * (1.0f / (float)PLANE);
    }
}

// ---------------------------------------------------------------------------
// Kernel 2: dynamic net. grid = (9, 32). Block (r0, b): recompute h (cheap),
// each thread computes one row r = r0*256+tid of wdyn[b]. w2 L2-resident.
// ---------------------------------------------------------------------------
__global__ __launch_bounds__(256) void dyn_kernel(const float* __restrict__ w1,
                                                  const float* __restrict__ b1,
                                                  const float* __restrict__ w2,
                                                  const float* __restrict__ b2) {
    const int b  = blockIdx.y;
    const int r0 = blockIdx.x;
    const int c  = threadIdx.x;
    __shared__ float ps[CC];
    __shared__ float hs[CC];
    ps[c] = g_pooled[b * CC + c];
    __syncthreads();

    {
        float acc = b1[c];
        const float4* __restrict__ wr =
            reinterpret_cast<const float4*>(w1 + (size_t)c * CC);
        const float4* __restrict__ pv = reinterpret_cast<const float4*>(ps);
#pragma unroll 8
        for (int k = 0; k < CC / 4; ++k) {
            float4 a = pv[k];
            float4 w = wr[k];
            acc += a.x * w.x + a.y * w.y + a.z * w.z + a.w * w.w;
        }
        hs[c] = 0.5f * acc * (1.0f + erff(acc * 0.70710678118654752f));
    }
    __syncthreads();

    const int r = r0 * 256 + c;
    float acc = b2[r];
    const float4* __restrict__ wr =
        reinterpret_cast<const float4*>(w2 + (size_t)r * CC);
    const float4* __restrict__ hv = reinterpret_cast<const float4*>(hs);
#pragma unroll 8
    for (int k = 0; k < CC / 4; ++k) {
        float4 a = hv[k];
        float4 w = wr[k];
        acc += a.x * w.x + a.y * w.y + a.z * w.z + a.w * w.w;
    }
    g_wdyn[(size_t)b * W2ROWS + r] = acc;
}

// ---------------------------------------------------------------------------
// Kernel 3 v4: smem-staged plane + register-sliding row window.
// Block = 1 plane, 288 threads = 24 strips x 12 row-chunks.
// Thread: 8 consecutive output rows, 10 smem row-loads (reuse across window).
// Planes processed in REVERSE order to hit the x-tail still resident in L2
// from pool_kernel.
// ---------------------------------------------------------------------------
struct Row6 { float4 c; float l, r; };

__device__ __forceinline__ Row6 load_row_s(const float* __restrict__ s,
                                           int y, int xb, int x4) {
    Row6 o;
    const float* rp = s + y * HWD;
    o.c = *reinterpret_cast<const float4*>(rp + xb);
    // horizontal reflect: left of col0 = col1 (c.y); right of col95 = col94 (c.z)
    o.l = (x4 == 0)        ? o.c.y : rp[xb - 1];
    o.r = (x4 == ROW4 - 1) ? o.c.z : rp[xb + 4];
    return o;
}

__device__ __forceinline__ void row_fma(float4& acc, const Row6& rr,
                                        float wl, float wc, float wr) {
    acc.x += rr.l   * wl + rr.c.x * wc + rr.c.y * wr;
    acc.y += rr.c.x * wl + rr.c.y * wc + rr.c.z * wr;
    acc.z += rr.c.y * wl + rr.c.z * wc + rr.c.w * wr;
    acc.w += rr.c.z * wl + rr.c.w * wc + rr.r   * wr;
}

__global__ __launch_bounds__(288) void conv_kernel(const float* __restrict__ x,
                                                   float* __restrict__ out) {
    const int plane = (NPLANES - 1) - blockIdx.x;   // reverse order: L2 reuse
    __shared__ float s[PLANE];
    const int tid = threadIdx.x;

    const float4* __restrict__ xp =
        reinterpret_cast<const float4*>(x + (size_t)plane * PLANE);
    float4* sp = reinterpret_cast<float4*>(s);
#pragma unroll
    for (int it = 0; it < 8; ++it)                  // 2304/288 = 8
        sp[tid + it * 288] = xp[tid + it * 288];

    float w[KK];
    const float* __restrict__ wd = g_wdyn + (size_t)plane * KK;
#pragma unroll
    for (int i = 0; i < KK; ++i) w[i] = wd[i];
    __syncthreads();

    const int x4 = tid % ROW4;      // strip 0..23
    const int cy = tid / ROW4;      // chunk 0..11
    const int y0 = cy * 8;
    const int xb = x4 * 4;

    // vertical reflect: row -1 -> 1 (only applies when cy==0)
    Row6 prev = load_row_s(s, (cy == 0) ? 1 : (y0 - 1), xb, x4);
    Row6 cur  = load_row_s(s, y0, xb, x4);

    float4* __restrict__ o4 =
        reinterpret_cast<float4*>(out + (size_t)plane * PLANE);

#pragma unroll
    for (int i = 0; i < 8; ++i) {
        const int y  = y0 + i;
        const int yn = (y == HWD - 1) ? HWD - 2 : y + 1;  // reflect 96 -> 94
        Row6 nxt = load_row_s(s, yn, xb, x4);
        float4 acc = make_float4(0.f, 0.f, 0.f, 0.f);
        row_fma(acc, prev, w[0], w[1], w[2]);
        row_fma(acc, cur,  w[3], w[4], w[5]);
        row_fma(acc, nxt,  w[6], w[7], w[8]);
        __stcs(&o4[y * ROW4 + x4], acc);
        prev = cur; cur = nxt;
    }
}

// ---------------------------------------------------------------------------
extern "C" void kernel_launch(void* const* d_in, const int* in_sizes, int n_in,
                              void* d_out, int out_size) {
    const float* x  = (const float*)d_in[0];   // (32,256,96,96)
    const float* w1 = (const float*)d_in[1];   // (256,256)
    const float* b1 = (const float*)d_in[2];   // (256,)
    const float* w2 = (const float*)d_in[3];   // (2304,256)
    const float* b2 = (const float*)d_in[4];   // (2304,)
    float* out = (float*)d_out;

    pool_kernel<<<NPLANES, 256>>>(x);
    dyn_kernel<<<dim3(KK, BB), 256>>>(w1, b1, w2, b2);
    conv_kernel<<<NPLANES, 288>>>(x, out);
}